// round 4
// baseline (speedup 1.0000x reference)
#include <cuda_runtime.h>
#include <cstdint>

#define FLOOR_V 1e-6f
#define MELS 128
#define FRAMES 1024

// One warp per (batch,time) row pair; software-pipelined grid-stride loop
// (prefetch next pair while processing current -> MLP 4). Closed-form
// separable replacement for the width-axis conv:
//   smoothed[w] = alpha^(511-w) * R / S,  R = sum_m x[m] * alpha^m
// Hot path: per-lane bound + warp vote proves every smoothed value clamps to
// FLOOR, so smoothed^-alpha == KA (warp-uniform). The epilogue is computed
// speculatively with KA (independent of the vote); the rare general path
// overwrites it.
__global__ __launch_bounds__(256)
void pcen_kernel(const float* __restrict__ in,
                 const float* __restrict__ p_alpha,
                 const float* __restrict__ p_delta,
                 const float* __restrict__ p_root,
                 float* __restrict__ out,
                 int num_rows) {
    const float alpha = __ldg(p_alpha);
    const float delta = __ldg(p_delta);
    const float root  = __ldg(p_root);

    const int lane = threadIdx.x & 31;
    const int warp_global = (blockIdx.x * blockDim.x + threadIdx.x) >> 5;
    const int nwarps = (gridDim.x * blockDim.x) >> 5;

    // ---- warp-invariant derived constants ----
    const float la = __log2f(alpha);
    float S;
    {
        const float one_minus_a = 1.0f - alpha;
        if (fabsf(one_minus_a) > 1e-12f)
            S = (1.0f - exp2f((float)FRAMES * la)) / one_minus_a;
        else
            S = (float)FRAMES;
    }
    const float KA    = __powf(FLOOR_V, -alpha);   // FLOOR^-alpha
    const float droot = __powf(delta, root);       // delta^root
    const float inv_S = 1.0f / S;
    const float ralpha = 1.0f / alpha;

    // Per-lane dot weights alpha^m for m = 4*lane + i
    const float w0 = exp2f((float)(4 * lane) * la);
    const float w1 = w0 * alpha;
    const float w2 = w1 * alpha;
    const float w3 = w2 * alpha;

    // Per-lane conv coefficients c_w = alpha^(511-w)/S (general path only)
    const float c0 = exp2f((float)((FRAMES / 2 - 1) - 4 * lane) * la) * inv_S;
    const float c1 = c0 * ralpha;
    const float c2 = c1 * ralpha;
    const float c3 = c2 * ralpha;

    // R <= 32*max_lane(part) => part <= FLOOR/(32*cb) proves all bins clamp.
    const float cb = fmaxf(exp2f((float)(FRAMES / 2 - 1) * la),
                           exp2f((float)(FRAMES / 2 - MELS) * la)) * inv_S;
    const float thresh = FLOOR_V / (32.0f * cb);

    const float4* __restrict__ in4  = reinterpret_cast<const float4*>(in);
    float4* __restrict__       out4 = reinterpret_cast<float4*>(out);

    const int npairs = num_rows >> 1;  // 65536 rows -> 32768 pairs

    int q = warp_global;
    float4 va, vb;
    if (q < npairs) {
        const int b = q * (MELS / 2) + lane;
        va = in4[b];
        vb = in4[b + (MELS / 4)];
    }

    while (q < npairs) {
        const int qn = q + nwarps;
        const float4 u0 = va, u1 = vb;
        // Prefetch next pair before any compute (overlaps DRAM latency)
        if (qn < npairs) {
            const int bn = qn * (MELS / 2) + lane;
            va = in4[bn];
            vb = in4[bn + (MELS / 4)];
        }

        float x00 = fmaxf(u0.x, FLOOR_V), x01 = fmaxf(u0.y, FLOOR_V);
        float x02 = fmaxf(u0.z, FLOOR_V), x03 = fmaxf(u0.w, FLOOR_V);
        float x10 = fmaxf(u1.x, FLOOR_V), x11 = fmaxf(u1.y, FLOOR_V);
        float x12 = fmaxf(u1.z, FLOOR_V), x13 = fmaxf(u1.w, FLOOR_V);

        // Speculative hot-path epilogue (depends only on x, not on the vote)
        float4 o0, o1;
        o0.x = __powf(fmaf(x00, KA, delta), root) - droot;
        o0.y = __powf(fmaf(x01, KA, delta), root) - droot;
        o0.z = __powf(fmaf(x02, KA, delta), root) - droot;
        o0.w = __powf(fmaf(x03, KA, delta), root) - droot;
        o1.x = __powf(fmaf(x10, KA, delta), root) - droot;
        o1.y = __powf(fmaf(x11, KA, delta), root) - droot;
        o1.z = __powf(fmaf(x12, KA, delta), root) - droot;
        o1.w = __powf(fmaf(x13, KA, delta), root) - droot;

        // Row-sum partials for the clamp proof (runs in parallel with MUFUs)
        float p0 = x00 * w0;
        p0 = fmaf(x01, w1, p0); p0 = fmaf(x02, w2, p0); p0 = fmaf(x03, w3, p0);
        float p1 = x10 * w0;
        p1 = fmaf(x11, w1, p1); p1 = fmaf(x12, w2, p1); p1 = fmaf(x13, w3, p1);

        if (!__all_sync(0xffffffffu, (p0 <= thresh) & (p1 <= thresh))) {
            // General path (not taken for this data): exact row sums,
            // per-bin smoothed, recompute outputs.
            float r0 = p0, r1 = p1;
#pragma unroll
            for (int s = 16; s >= 1; s >>= 1) {
                r0 += __shfl_xor_sync(0xffffffffu, r0, s);
                r1 += __shfl_xor_sync(0xffffffffu, r1, s);
            }
            float pm00 = __powf(fmaxf(c0 * r0, FLOOR_V), -alpha);
            float pm01 = __powf(fmaxf(c1 * r0, FLOOR_V), -alpha);
            float pm02 = __powf(fmaxf(c2 * r0, FLOOR_V), -alpha);
            float pm03 = __powf(fmaxf(c3 * r0, FLOOR_V), -alpha);
            float pm10 = __powf(fmaxf(c0 * r1, FLOOR_V), -alpha);
            float pm11 = __powf(fmaxf(c1 * r1, FLOOR_V), -alpha);
            float pm12 = __powf(fmaxf(c2 * r1, FLOOR_V), -alpha);
            float pm13 = __powf(fmaxf(c3 * r1, FLOOR_V), -alpha);
            o0.x = __powf(fmaf(x00, pm00, delta), root) - droot;
            o0.y = __powf(fmaf(x01, pm01, delta), root) - droot;
            o0.z = __powf(fmaf(x02, pm02, delta), root) - droot;
            o0.w = __powf(fmaf(x03, pm03, delta), root) - droot;
            o1.x = __powf(fmaf(x10, pm10, delta), root) - droot;
            o1.y = __powf(fmaf(x11, pm11, delta), root) - droot;
            o1.z = __powf(fmaf(x12, pm12, delta), root) - droot;
            o1.w = __powf(fmaf(x13, pm13, delta), root) - droot;
        }

        const int b = q * (MELS / 2) + lane;
        out4[b] = o0;
        out4[b + (MELS / 4)] = o1;
        q = qn;
    }

    // Tail (odd num_rows): single-row path
    for (int row = (npairs << 1) + warp_global; row < num_rows; row += nwarps) {
        const int idx = row * (MELS / 4) + lane;
        const float4 v = in4[idx];
        float x0 = fmaxf(v.x, FLOOR_V), x1 = fmaxf(v.y, FLOOR_V);
        float x2 = fmaxf(v.z, FLOOR_V), x3 = fmaxf(v.w, FLOOR_V);
        float p = x0 * w0;
        p = fmaf(x1, w1, p); p = fmaf(x2, w2, p); p = fmaf(x3, w3, p);
        float pm0 = KA, pm1 = KA, pm2 = KA, pm3 = KA;
        if (!__all_sync(0xffffffffu, p <= thresh)) {
            float r = p;
#pragma unroll
            for (int s = 16; s >= 1; s >>= 1)
                r += __shfl_xor_sync(0xffffffffu, r, s);
            pm0 = __powf(fmaxf(c0 * r, FLOOR_V), -alpha);
            pm1 = __powf(fmaxf(c1 * r, FLOOR_V), -alpha);
            pm2 = __powf(fmaxf(c2 * r, FLOOR_V), -alpha);
            pm3 = __powf(fmaxf(c3 * r, FLOOR_V), -alpha);
        }
        float4 o;
        o.x = __powf(fmaf(x0, pm0, delta), root) - droot;
        o.y = __powf(fmaf(x1, pm1, delta), root) - droot;
        o.z = __powf(fmaf(x2, pm2, delta), root) - droot;
        o.w = __powf(fmaf(x3, pm3, delta), root) - droot;
        out4[idx] = o;
    }
}

extern "C" void kernel_launch(void* const* d_in, const int* in_sizes, int n_in,
                              void* d_out, int out_size) {
    const float* inputs = (const float*)d_in[0];
    const float* alpha  = (const float*)d_in[1];
    const float* delta  = (const float*)d_in[2];
    const float* root   = (const float*)d_in[3];
    float* out = (float*)d_out;

    const int num_rows = in_sizes[0] / MELS;  // 64 * 1024 = 65536

    const int threads = 256;

    // Exactly one resident wave: blocks = SMs * max-resident-blocks for the
    // compiled regcount (kills the R3 partial-second-wave tail).
    int dev = 0, sms = 148, max_blocks = 5;
    cudaGetDevice(&dev);
    cudaDeviceGetAttribute(&sms, cudaDevAttrMultiProcessorCount, dev);
    cudaOccupancyMaxActiveBlocksPerMultiprocessor(&max_blocks, pcen_kernel,
                                                  threads, 0);
    int blocks = sms * (max_blocks > 0 ? max_blocks : 1);
    const int max_useful = (num_rows / 2 + (threads / 32) - 1) / (threads / 32);
    if (blocks > max_useful) blocks = max_useful;

    pcen_kernel<<<blocks, threads>>>(inputs, alpha, delta, root, out, num_rows);
}